// round 1
// baseline (speedup 1.0000x reference)
#include <cuda_runtime.h>

// out = kipf - lbda[row] * input
// input, kipf: [N_NODES=100000, N_FEATURES=256] fp32
// lbda: [N_NODES] fp32
// Vectorized float4: 64 float4 per row, 6.4M float4 total.

__global__ __launch_bounds__(256) void damping_kernel(
    const float4* __restrict__ input4,
    const float4* __restrict__ kipf4,
    const float*  __restrict__ lbda,
    float4* __restrict__ out4,
    int n4)  // total float4 count
{
    int i = blockIdx.x * blockDim.x + threadIdx.x;
    if (i >= n4) return;

    int row = i >> 6;               // 256 floats / 4 = 64 float4 per row
    float l = __ldg(&lbda[row]);    // broadcast across 64 consecutive threads

    float4 a = input4[i];
    float4 k = kipf4[i];

    float4 r;
    r.x = fmaf(-l, a.x, k.x);
    r.y = fmaf(-l, a.y, k.y);
    r.z = fmaf(-l, a.z, k.z);
    r.w = fmaf(-l, a.w, k.w);

    out4[i] = r;
}

extern "C" void kernel_launch(void* const* d_in, const int* in_sizes, int n_in,
                              void* d_out, int out_size) {
    const float4* input4 = (const float4*)d_in[0];   // input_term
    const float4* kipf4  = (const float4*)d_in[1];   // kipf_term
    const float*  lbda   = (const float*)d_in[2];    // lbda
    // d_in[3] is spar (unused scalar, always 1)

    int n  = out_size;        // 100000 * 256
    int n4 = n / 4;           // 6,400,000

    int threads = 256;
    int blocks  = (n4 + threads - 1) / threads;  // 25000
    damping_kernel<<<blocks, threads>>>(input4, kipf4, lbda, (float4*)d_out, n4);
}